// round 9
// baseline (speedup 1.0000x reference)
#include <cuda_runtime.h>
#include <cuda_bf16.h>
#include <math.h>

// Problem constants (match reference)
#define NN 50000
#define EE 1600000
#define FIN 256
#define HH 128
#define CC 40
#define NP 50048            // NN padded to multiple of 128 (pad rows stay 0)

// ---------------- device scratch (no allocs allowed) ----------------
__device__ __align__(16) float g_xT[(size_t)HH * NP];  // feature-major buffer A
__device__ __align__(16) float g_hT[(size_t)HH * NP];  // feature-major buffer B
__device__ int   g_deg[NN];           // zero at load; scan re-zeroes after use
__device__ int   g_rowptr[NN + 1];
__device__ int   g_cursor[NN];
__device__ __align__(16) int2 g_edge[EE];   // ((dst<<16)|src, float_bits(w)) sorted by dst
__device__ float g_Wc[CC * CC];
__device__ float g_cbias[CC];

// ---------------- CSR build ----------------
__global__ void hist_kernel(const int* __restrict__ dst, int e) {
    int i = blockIdx.x * blockDim.x + threadIdx.x;
    if (i < e) atomicAdd(&g_deg[dst[i]], 1);
}
__global__ void scan_kernel(int n) {
    __shared__ int wsum[32];
    __shared__ int s_run;
    int tid = threadIdx.x, lane = tid & 31, wid = tid >> 5;
    if (tid == 0) s_run = 0;
    __syncthreads();
    for (int base = 0; base < n; base += 1024) {
        int idx = base + tid;
        int v = 0;
        if (idx < n) { v = g_deg[idx]; g_deg[idx] = 0; }
        int inc = v;
        #pragma unroll
        for (int off = 1; off < 32; off <<= 1) {
            int t = __shfl_up_sync(0xffffffffu, inc, off);
            if (lane >= off) inc += t;
        }
        if (lane == 31) wsum[wid] = inc;
        __syncthreads();
        if (wid == 0) {
            int x = wsum[lane];
            #pragma unroll
            for (int off = 1; off < 32; off <<= 1) {
                int t = __shfl_up_sync(0xffffffffu, x, off);
                if (lane >= off) x += t;
            }
            wsum[lane] = x;
        }
        __syncthreads();
        int woff = (wid > 0) ? wsum[wid - 1] : 0;
        int run = s_run;
        int excl = run + woff + inc - v;
        if (idx < n) { g_rowptr[idx] = excl; g_cursor[idx] = excl; }
        __syncthreads();
        if (tid == 0) s_run = run + wsum[31];
        __syncthreads();
    }
    if (threadIdx.x == 0) g_rowptr[n] = s_run;
}
__global__ void scatter_kernel(const int* __restrict__ src, const int* __restrict__ dst,
                               const float* __restrict__ w, int e) {
    int i = blockIdx.x * blockDim.x + threadIdx.x;
    if (i < e) {
        int d = dst[i];
        int pos = atomicAdd(&g_cursor[d], 1);
        g_edge[pos] = make_int2((d << 16) | src[i], __float_as_int(w[i]));
    }
}

// ---------------- GEMM with transposed (feature-major) output ----------------
#define GBM 128
#define GBN 64
#define GBK 8
template<bool NORM, bool AFM>
__global__ __launch_bounds__(256, 3) void gemmT_kernel(
    const float* __restrict__ A, const float* __restrict__ B,
    float* __restrict__ CT, int M, int K)
{
    __shared__ float As[2][GBK][GBM + 4];
    __shared__ float Bs[2][GBK][GBN];
    __shared__ float sT[GBN][GBM + 1];
    __shared__ float s_invs[GBM];
    int tid = threadIdx.x;
    int m0 = blockIdx.x * GBM;
    int n0 = blockIdx.y * GBN;
    int tx = tid & 15, ty = tid >> 4;

    int arow = tid >> 1;
    int ahalf = (tid & 1) * 4;
    bool aok = (m0 + arow) < M;
    const float* Aptr = A + (size_t)(m0 + arow) * K + ahalf;
    int akk = tid >> 5;
    int ac4 = (tid & 31) * 4;
    const float* AptrF = A + (size_t)akk * NP + m0 + ac4;
    int brow = tid >> 5;
    int bcol = (tid & 31) * 2;
    const float* Bptr = B + (size_t)brow * HH + n0 + bcol;

    float acc[8][4];
    #pragma unroll
    for (int i = 0; i < 8; i++)
        #pragma unroll
        for (int j = 0; j < 4; j++) acc[i][j] = 0.0f;
    float ssq = 0.0f;

    float4 areg;
    if (AFM) {
        areg = *(const float4*)AptrF;
    } else {
        areg = make_float4(0.f, 0.f, 0.f, 0.f);
        if (aok) areg = *(const float4*)Aptr;
        if (NORM) ssq += areg.x*areg.x + areg.y*areg.y + areg.z*areg.z + areg.w*areg.w;
    }
    float2 breg = *(const float2*)Bptr;

    if (AFM) {
        *(float4*)&As[0][akk][ac4] = areg;
    } else {
        As[0][ahalf + 0][arow] = areg.x;
        As[0][ahalf + 1][arow] = areg.y;
        As[0][ahalf + 2][arow] = areg.z;
        As[0][ahalf + 3][arow] = areg.w;
    }
    Bs[0][brow][bcol] = breg.x;
    Bs[0][brow][bcol + 1] = breg.y;
    __syncthreads();

    int buf = 0;
    for (int k0 = GBK; k0 < K; k0 += GBK) {
        if (AFM) {
            areg = *(const float4*)(AptrF + (size_t)k0 * NP);
        } else {
            areg = make_float4(0.f, 0.f, 0.f, 0.f);
            if (aok) areg = *(const float4*)(Aptr + k0);
            if (NORM) ssq += areg.x*areg.x + areg.y*areg.y + areg.z*areg.z + areg.w*areg.w;
        }
        breg = *(const float2*)(Bptr + (size_t)k0 * HH);

        #pragma unroll
        for (int kk = 0; kk < GBK; kk++) {
            float ra[8], rb[4];
            *(float4*)(ra)     = *(const float4*)&As[buf][kk][ty * 8];
            *(float4*)(ra + 4) = *(const float4*)&As[buf][kk][ty * 8 + 4];
            *(float4*)(rb)     = *(const float4*)&Bs[buf][kk][tx * 4];
            #pragma unroll
            for (int i = 0; i < 8; i++)
                #pragma unroll
                for (int j = 0; j < 4; j++) acc[i][j] += ra[i] * rb[j];
        }
        int nb = buf ^ 1;
        if (AFM) {
            *(float4*)&As[nb][akk][ac4] = areg;
        } else {
            As[nb][ahalf + 0][arow] = areg.x;
            As[nb][ahalf + 1][arow] = areg.y;
            As[nb][ahalf + 2][arow] = areg.z;
            As[nb][ahalf + 3][arow] = areg.w;
        }
        Bs[nb][brow][bcol] = breg.x;
        Bs[nb][brow][bcol + 1] = breg.y;
        __syncthreads();
        buf = nb;
    }
    #pragma unroll
    for (int kk = 0; kk < GBK; kk++) {
        float ra[8], rb[4];
        *(float4*)(ra)     = *(const float4*)&As[buf][kk][ty * 8];
        *(float4*)(ra + 4) = *(const float4*)&As[buf][kk][ty * 8 + 4];
        *(float4*)(rb)     = *(const float4*)&Bs[buf][kk][tx * 4];
        #pragma unroll
        for (int i = 0; i < 8; i++)
            #pragma unroll
            for (int j = 0; j < 4; j++) acc[i][j] += ra[i] * rb[j];
    }

    if (NORM) {
        float tot = ssq + __shfl_xor_sync(0xffffffffu, ssq, 1);
        s_invs[arow] = 1.0f / fmaxf(sqrtf(tot), 1e-12f);
    }
    __syncthreads();

    #pragma unroll
    for (int i = 0; i < 8; i++) {
        float s = NORM ? s_invs[ty * 8 + i] : 1.0f;
        #pragma unroll
        for (int j = 0; j < 4; j++) sT[tx * 4 + j][ty * 8 + i] = acc[i][j] * s;
    }
    __syncthreads();
    #pragma unroll
    for (int t = 0; t < 32; t++) {
        int lin = tid + t * 256;
        int c = lin >> 7;
        int r = lin & 127;
        int gr = m0 + r;
        if (gr < M) CT[(size_t)(n0 + c) * NP + gr] = sT[c][r];
    }
}

// ---------------- edge-parallel feature-major SPMM ----------------
// One CTA per feature f. sx = xT[f][:] in smem. Each warp streams a contiguous
// chunk of the dst-sorted edge list (coalesced), computes w*sx[src], does a
// warp segmented sum over equal dst, and atomically adds per-segment results.
template<bool RELU>
__global__ __launch_bounds__(1024) void spmm_edge_kernel(
    const float* __restrict__ xT, float* __restrict__ outT,
    const float* __restrict__ bias, int n, int e)
{
    extern __shared__ float sx[];
    int f = blockIdx.x;
    const float* xrow = xT + (size_t)f * NP;
    float* orow = outT + (size_t)f * NP;
    int tid = threadIdx.x;

    for (int i = tid; i < n; i += 1024) sx[i] = xrow[i];
    float b = bias[f];
    for (int i = tid; i < n; i += 1024) orow[i] = b;   // init with bias
    __syncthreads();   // orders smem fill + global init before atomics

    int warp = tid >> 5, lane = tid & 31;
    size_t start = ((size_t)warp * e) >> 5;
    size_t end   = ((size_t)(warp + 1) * e) >> 5;
    for (size_t base = start; base < end; base += 32) {
        size_t idx = base + lane;
        bool valid = idx < end;
        unsigned key = 0xFFFFFFFFu;
        float val = 0.f;
        if (valid) {
            int2 ed = g_edge[idx];
            unsigned sd = (unsigned)ed.x;
            key = sd >> 16;
            val = __int_as_float(ed.y) * sx[sd & 0xFFFFu];
        }
        #pragma unroll
        for (int off = 1; off < 32; off <<= 1) {
            float up = __shfl_up_sync(0xffffffffu, val, off);
            unsigned kup = __shfl_up_sync(0xffffffffu, key, off);
            if (lane >= off && kup == key) val += up;
        }
        unsigned knext = __shfl_down_sync(0xffffffffu, key, 1);
        bool lastv = (lane == 31) || (knext != key);
        if (valid && lastv) atomicAdd(&orow[key], val);
    }
    if (RELU) {
        __threadfence();    // make this thread's atomics visible
        __syncthreads();    // all threads' atomics done
        for (int i = tid; i < n; i += 1024) {
            float v = __ldcg(&orow[i]);   // bypass stale L1 (atomics landed in L2)
            orow[i] = fmaxf(v, 0.f);
        }
    }
}

// ---------------- head weight pre-combine ----------------
__global__ void wcomb_kernel(const float* __restrict__ We, const float* __restrict__ be,
                             const float* __restrict__ Wf, const float* __restrict__ bf)
{
    int t = blockIdx.x * blockDim.x + threadIdx.x;
    if (t < CC * CC) {
        int i = t / CC, c = t % CC;
        float s = 0.f;
        for (int k = 0; k < HH; k++) s += We[i * HH + k] * Wf[k * CC + c];
        g_Wc[t] = s;
    }
    if (t < CC) {
        float s = bf[t];
        for (int k = 0; k < HH; k++) s += be[k] * Wf[k * CC + t];
        g_cbias[t] = s;
    }
}

// ---------------- fused head: logits = y@Wc + h@Wf_bot + cbias ; softmax ----------------
__global__ __launch_bounds__(128) void head_kernel(
    const float* __restrict__ hT, const float* __restrict__ yin,
    const float* __restrict__ Wf, float* __restrict__ out, int n)
{
    __shared__ float sWfb[HH * CC];
    __shared__ float sWc[CC * CC];
    __shared__ float sh[32 * 129];
    __shared__ float sl[32 * CC];
    __shared__ float smax[32], sinv[32];
    int tid = threadIdx.x;
    int r0 = blockIdx.x * 32;
    int rows = min(32, n - r0);

    for (int i = tid; i < HH * CC; i += 128) sWfb[i] = Wf[HH * CC + i];
    for (int i = tid; i < CC * CC; i += 128) sWc[i] = g_Wc[i];
    for (int i = tid; i < 32 * HH; i += 128) {
        int k = i >> 5, r = i & 31;
        if (r < rows) sh[r * 129 + k] = hT[(size_t)k * NP + r0 + r];
    }
    __syncthreads();

    int r = tid >> 2, q = tid & 3, c0 = q * 10;
    if (r < rows) {
        float acc[10];
        #pragma unroll
        for (int j = 0; j < 10; j++) acc[j] = g_cbias[c0 + j];
        for (int k = 0; k < HH; k++) {
            float hv = sh[r * 129 + k];
            #pragma unroll
            for (int j = 0; j < 10; j++) acc[j] += hv * sWfb[k * CC + c0 + j];
        }
        const float* yr = yin + (size_t)(r0 + r) * CC;
        for (int k = 0; k < CC; k++) {
            float yv = yr[k];
            #pragma unroll
            for (int j = 0; j < 10; j++) acc[j] += yv * sWc[k * CC + c0 + j];
        }
        #pragma unroll
        for (int j = 0; j < 10; j++) sl[r * CC + c0 + j] = acc[j];
    }
    __syncthreads();
    if (tid < 32 && tid < rows) {
        float m = -1e30f;
        for (int c = 0; c < CC; c++) m = fmaxf(m, sl[tid * CC + c]);
        float s = 0.f;
        for (int c = 0; c < CC; c++) s += __expf(sl[tid * CC + c] - m);
        smax[tid] = m;
        sinv[tid] = 1.0f / s;
    }
    __syncthreads();
    int tot = rows * CC;
    for (int i = tid; i < tot; i += 128) {
        int rr = i / CC;
        out[(size_t)r0 * CC + i] = __expf(sl[i] - smax[rr]) * sinv[rr];
    }
}

// ---------------- launch ----------------
#define SPMM_SMEM (NN * 4)   // 200000 B < 227KB cap

extern "C" void kernel_launch(void* const* d_in, const int* in_sizes, int n_in,
                              void* d_out, int out_size)
{
    const float* features = (const float*)d_in[0];
    const int*   src      = (const int*)  d_in[1];
    const int*   dst      = (const int*)  d_in[2];
    const float* ew       = (const float*)d_in[3];
    const float* y        = (const float*)d_in[4];
    const float* W1       = (const float*)d_in[5];
    const float* b1       = (const float*)d_in[6];
    const float* W2       = (const float*)d_in[7];
    const float* b2       = (const float*)d_in[8];
    const float* We       = (const float*)d_in[9];
    const float* be       = (const float*)d_in[10];
    const float* Wf       = (const float*)d_in[11];
    const float* bf       = (const float*)d_in[12];
    float* out = (float*)d_out;

    int n = in_sizes[0] / FIN;     // 50000
    int e = in_sizes[1];           // 1600000

    cudaFuncSetAttribute(spmm_edge_kernel<true>,  cudaFuncAttributeMaxDynamicSharedMemorySize, SPMM_SMEM);
    cudaFuncSetAttribute(spmm_edge_kernel<false>, cudaFuncAttributeMaxDynamicSharedMemorySize, SPMM_SMEM);

    int edgeBlocks = (e + 255) / 256;
    dim3 gemmGrid(NP / GBM, HH / GBN);   // 391 x 2

    hist_kernel<<<edgeBlocks, 256>>>(dst, e);                                  // 1
    scan_kernel<<<1, 1024>>>(n);                                               // 2
    scatter_kernel<<<edgeBlocks, 256>>>(src, dst, ew, e);                      // 3
    gemmT_kernel<true,  false><<<gemmGrid, 256>>>(features, W1, g_xT, n, FIN); // 4  <-- profiled (real)
    spmm_edge_kernel<true><<<HH, 1024, SPMM_SMEM>>>(g_xT, g_hT, b1, n, e);     // 5
    gemmT_kernel<false, true ><<<gemmGrid, 256>>>(g_hT, W2, g_xT, n, HH);      // 6
    spmm_edge_kernel<false><<<HH, 1024, SPMM_SMEM>>>(g_xT, g_hT, b2, n, e);    // 7
    wcomb_kernel<<<7, 256>>>(We, be, Wf, bf);                                  // 8
    head_kernel<<<(n + 31) / 32, 128>>>(g_hT, y, Wf, out, n);                  // 9
}

// round 10
// speedup vs baseline: 1.3738x; 1.3738x over previous
#include <cuda_runtime.h>
#include <cuda_bf16.h>
#include <math.h>

// Problem constants (match reference)
#define NN 50000
#define EE 1600000
#define FIN 256
#define HH 128
#define CC 40
#define NP 50048            // NN padded to multiple of 128 (pad rows stay 0)

// ---------------- device scratch (no allocs allowed) ----------------
__device__ __align__(16) float g_xT[(size_t)HH * NP];  // feature-major buffer A
__device__ __align__(16) float g_hT[(size_t)HH * NP];  // feature-major buffer B
__device__ int   g_deg[NN];           // zero at load; scan re-zeroes after use
__device__ int   g_rowptr[NN + 1];
__device__ int   g_cursor[NN];
__device__ __align__(16) int2 g_edge[EE];   // ((dst<<16)|src, float_bits(w)) sorted by dst
__device__ float g_Wc[CC * CC];
__device__ float g_cbias[CC];

// ---------------- CSR build ----------------
__global__ void hist_kernel(const int* __restrict__ dst, int e) {
    int i = blockIdx.x * blockDim.x + threadIdx.x;
    if (i < e) atomicAdd(&g_deg[dst[i]], 1);
}
__global__ void scan_kernel(int n) {
    __shared__ int wsum[32];
    __shared__ int s_run;
    int tid = threadIdx.x, lane = tid & 31, wid = tid >> 5;
    if (tid == 0) s_run = 0;
    __syncthreads();
    for (int base = 0; base < n; base += 1024) {
        int idx = base + tid;
        int v = 0;
        if (idx < n) { v = g_deg[idx]; g_deg[idx] = 0; }
        int inc = v;
        #pragma unroll
        for (int off = 1; off < 32; off <<= 1) {
            int t = __shfl_up_sync(0xffffffffu, inc, off);
            if (lane >= off) inc += t;
        }
        if (lane == 31) wsum[wid] = inc;
        __syncthreads();
        if (wid == 0) {
            int x = wsum[lane];
            #pragma unroll
            for (int off = 1; off < 32; off <<= 1) {
                int t = __shfl_up_sync(0xffffffffu, x, off);
                if (lane >= off) x += t;
            }
            wsum[lane] = x;
        }
        __syncthreads();
        int woff = (wid > 0) ? wsum[wid - 1] : 0;
        int run = s_run;
        int excl = run + woff + inc - v;
        if (idx < n) { g_rowptr[idx] = excl; g_cursor[idx] = excl; }
        __syncthreads();
        if (tid == 0) s_run = run + wsum[31];
        __syncthreads();
    }
    if (threadIdx.x == 0) g_rowptr[n] = s_run;
}
__global__ void scatter_kernel(const int* __restrict__ src, const int* __restrict__ dst,
                               const float* __restrict__ w, int e) {
    int i = blockIdx.x * blockDim.x + threadIdx.x;
    if (i < e) {
        int d = dst[i];
        int pos = atomicAdd(&g_cursor[d], 1);
        g_edge[pos] = make_int2((d << 16) | src[i], __float_as_int(w[i]));
    }
}

// ---------------- GEMM with transposed (feature-major) output ----------------
#define GBM 128
#define GBN 64
#define GBK 8
template<bool NORM, bool AFM>
__global__ __launch_bounds__(256, 3) void gemmT_kernel(
    const float* __restrict__ A, const float* __restrict__ B,
    float* __restrict__ CT, int M, int K)
{
    __shared__ float As[2][GBK][GBM + 4];
    __shared__ float Bs[2][GBK][GBN];
    __shared__ float sT[GBN][GBM + 1];
    __shared__ float s_invs[GBM];
    int tid = threadIdx.x;
    int m0 = blockIdx.x * GBM;
    int n0 = blockIdx.y * GBN;
    int tx = tid & 15, ty = tid >> 4;

    int arow = tid >> 1;
    int ahalf = (tid & 1) * 4;
    bool aok = (m0 + arow) < M;
    const float* Aptr = A + (size_t)(m0 + arow) * K + ahalf;
    int akk = tid >> 5;
    int ac4 = (tid & 31) * 4;
    const float* AptrF = A + (size_t)akk * NP + m0 + ac4;
    int brow = tid >> 5;
    int bcol = (tid & 31) * 2;
    const float* Bptr = B + (size_t)brow * HH + n0 + bcol;

    float acc[8][4];
    #pragma unroll
    for (int i = 0; i < 8; i++)
        #pragma unroll
        for (int j = 0; j < 4; j++) acc[i][j] = 0.0f;
    float ssq = 0.0f;

    float4 areg;
    if (AFM) {
        areg = *(const float4*)AptrF;
    } else {
        areg = make_float4(0.f, 0.f, 0.f, 0.f);
        if (aok) areg = *(const float4*)Aptr;
        if (NORM) ssq += areg.x*areg.x + areg.y*areg.y + areg.z*areg.z + areg.w*areg.w;
    }
    float2 breg = *(const float2*)Bptr;

    if (AFM) {
        *(float4*)&As[0][akk][ac4] = areg;
    } else {
        As[0][ahalf + 0][arow] = areg.x;
        As[0][ahalf + 1][arow] = areg.y;
        As[0][ahalf + 2][arow] = areg.z;
        As[0][ahalf + 3][arow] = areg.w;
    }
    Bs[0][brow][bcol] = breg.x;
    Bs[0][brow][bcol + 1] = breg.y;
    __syncthreads();

    int buf = 0;
    for (int k0 = GBK; k0 < K; k0 += GBK) {
        if (AFM) {
            areg = *(const float4*)(AptrF + (size_t)k0 * NP);
        } else {
            areg = make_float4(0.f, 0.f, 0.f, 0.f);
            if (aok) areg = *(const float4*)(Aptr + k0);
            if (NORM) ssq += areg.x*areg.x + areg.y*areg.y + areg.z*areg.z + areg.w*areg.w;
        }
        breg = *(const float2*)(Bptr + (size_t)k0 * HH);

        #pragma unroll
        for (int kk = 0; kk < GBK; kk++) {
            float ra[8], rb[4];
            *(float4*)(ra)     = *(const float4*)&As[buf][kk][ty * 8];
            *(float4*)(ra + 4) = *(const float4*)&As[buf][kk][ty * 8 + 4];
            *(float4*)(rb)     = *(const float4*)&Bs[buf][kk][tx * 4];
            #pragma unroll
            for (int i = 0; i < 8; i++)
                #pragma unroll
                for (int j = 0; j < 4; j++) acc[i][j] += ra[i] * rb[j];
        }
        int nb = buf ^ 1;
        if (AFM) {
            *(float4*)&As[nb][akk][ac4] = areg;
        } else {
            As[nb][ahalf + 0][arow] = areg.x;
            As[nb][ahalf + 1][arow] = areg.y;
            As[nb][ahalf + 2][arow] = areg.z;
            As[nb][ahalf + 3][arow] = areg.w;
        }
        Bs[nb][brow][bcol] = breg.x;
        Bs[nb][brow][bcol + 1] = breg.y;
        __syncthreads();
        buf = nb;
    }
    #pragma unroll
    for (int kk = 0; kk < GBK; kk++) {
        float ra[8], rb[4];
        *(float4*)(ra)     = *(const float4*)&As[buf][kk][ty * 8];
        *(float4*)(ra + 4) = *(const float4*)&As[buf][kk][ty * 8 + 4];
        *(float4*)(rb)     = *(const float4*)&Bs[buf][kk][tx * 4];
        #pragma unroll
        for (int i = 0; i < 8; i++)
            #pragma unroll
            for (int j = 0; j < 4; j++) acc[i][j] += ra[i] * rb[j];
    }

    if (NORM) {
        float tot = ssq + __shfl_xor_sync(0xffffffffu, ssq, 1);
        s_invs[arow] = 1.0f / fmaxf(sqrtf(tot), 1e-12f);
    }
    __syncthreads();

    #pragma unroll
    for (int i = 0; i < 8; i++) {
        float s = NORM ? s_invs[ty * 8 + i] : 1.0f;
        #pragma unroll
        for (int j = 0; j < 4; j++) sT[tx * 4 + j][ty * 8 + i] = acc[i][j] * s;
    }
    __syncthreads();
    #pragma unroll
    for (int t = 0; t < 32; t++) {
        int lin = tid + t * 256;
        int c = lin >> 7;
        int r = lin & 127;
        int gr = m0 + r;
        if (gr < M) CT[(size_t)(n0 + c) * NP + gr] = sT[c][r];
    }
}

// ---------------- warp-per-row feature-major SPMM ----------------
// One CTA per feature f; sx = xT[f][:] in smem (200KB). Each warp takes rows
// warp, warp+32, ...: the row's contiguous edges are loaded coalesced
// (one warp-load covers 32 edges = 2 lines), each lane does w*sx[src] (LDS),
// then a 5-step butterfly reduce; lane0 writes bias+sum (+ReLU).
template<bool RELU>
__global__ __launch_bounds__(1024) void spmmW_kernel(
    const float* __restrict__ xT, float* __restrict__ outT,
    const float* __restrict__ bias, int n)
{
    extern __shared__ float sx[];
    int f = blockIdx.x;
    const float* xrow = xT + (size_t)f * NP;
    for (int i = threadIdx.x; i < n; i += 1024) sx[i] = xrow[i];
    __syncthreads();
    float b = bias[f];
    float* orow = outT + (size_t)f * NP;
    int warp = threadIdx.x >> 5, lane = threadIdx.x & 31;

    for (int row = warp; row < n; row += 32) {
        int e0 = g_rowptr[row], e1 = g_rowptr[row + 1];
        float acc = 0.f;
        for (int e = e0 + lane; e < e1; e += 32) {
            int2 ed = g_edge[e];
            acc += __int_as_float(ed.y) * sx[(unsigned)ed.x & 0xFFFFu];
        }
        #pragma unroll
        for (int off = 16; off > 0; off >>= 1)
            acc += __shfl_xor_sync(0xffffffffu, acc, off);
        if (lane == 0) {
            float v = acc + b;
            if (RELU) v = fmaxf(v, 0.f);
            orow[row] = v;
        }
    }
}

// ---------------- head weight pre-combine ----------------
__global__ void wcomb_kernel(const float* __restrict__ We, const float* __restrict__ be,
                             const float* __restrict__ Wf, const float* __restrict__ bf)
{
    int t = blockIdx.x * blockDim.x + threadIdx.x;
    if (t < CC * CC) {
        int i = t / CC, c = t % CC;
        float s = 0.f;
        for (int k = 0; k < HH; k++) s += We[i * HH + k] * Wf[k * CC + c];
        g_Wc[t] = s;
    }
    if (t < CC) {
        float s = bf[t];
        for (int k = 0; k < HH; k++) s += be[k] * Wf[k * CC + t];
        g_cbias[t] = s;
    }
}

// ---------------- fused head: logits = y@Wc + h@Wf_bot + cbias ; softmax ----------------
__global__ __launch_bounds__(128) void head_kernel(
    const float* __restrict__ hT, const float* __restrict__ yin,
    const float* __restrict__ Wf, float* __restrict__ out, int n)
{
    __shared__ float sWfb[HH * CC];
    __shared__ float sWc[CC * CC];
    __shared__ float sh[32 * 129];
    __shared__ float sl[32 * CC];
    __shared__ float smax[32], sinv[32];
    int tid = threadIdx.x;
    int r0 = blockIdx.x * 32;
    int rows = min(32, n - r0);

    for (int i = tid; i < HH * CC; i += 128) sWfb[i] = Wf[HH * CC + i];
    for (int i = tid; i < CC * CC; i += 128) sWc[i] = g_Wc[i];
    for (int i = tid; i < 32 * HH; i += 128) {
        int k = i >> 5, r = i & 31;
        if (r < rows) sh[r * 129 + k] = hT[(size_t)k * NP + r0 + r];
    }
    __syncthreads();

    int r = tid >> 2, q = tid & 3, c0 = q * 10;
    if (r < rows) {
        float acc[10];
        #pragma unroll
        for (int j = 0; j < 10; j++) acc[j] = g_cbias[c0 + j];
        for (int k = 0; k < HH; k++) {
            float hv = sh[r * 129 + k];
            #pragma unroll
            for (int j = 0; j < 10; j++) acc[j] += hv * sWfb[k * CC + c0 + j];
        }
        const float* yr = yin + (size_t)(r0 + r) * CC;
        for (int k = 0; k < CC; k++) {
            float yv = yr[k];
            #pragma unroll
            for (int j = 0; j < 10; j++) acc[j] += yv * sWc[k * CC + c0 + j];
        }
        #pragma unroll
        for (int j = 0; j < 10; j++) sl[r * CC + c0 + j] = acc[j];
    }
    __syncthreads();
    if (tid < 32 && tid < rows) {
        float m = -1e30f;
        for (int c = 0; c < CC; c++) m = fmaxf(m, sl[tid * CC + c]);
        float s = 0.f;
        for (int c = 0; c < CC; c++) s += __expf(sl[tid * CC + c] - m);
        smax[tid] = m;
        sinv[tid] = 1.0f / s;
    }
    __syncthreads();
    int tot = rows * CC;
    for (int i = tid; i < tot; i += 128) {
        int rr = i / CC;
        out[(size_t)r0 * CC + i] = __expf(sl[i] - smax[rr]) * sinv[rr];
    }
}

// ---------------- launch ----------------
#define SPMM_SMEM (NN * 4)   // 200000 B < 227KB cap

extern "C" void kernel_launch(void* const* d_in, const int* in_sizes, int n_in,
                              void* d_out, int out_size)
{
    const float* features = (const float*)d_in[0];
    const int*   src      = (const int*)  d_in[1];
    const int*   dst      = (const int*)  d_in[2];
    const float* ew       = (const float*)d_in[3];
    const float* y        = (const float*)d_in[4];
    const float* W1       = (const float*)d_in[5];
    const float* b1       = (const float*)d_in[6];
    const float* W2       = (const float*)d_in[7];
    const float* b2       = (const float*)d_in[8];
    const float* We       = (const float*)d_in[9];
    const float* be       = (const float*)d_in[10];
    const float* Wf       = (const float*)d_in[11];
    const float* bf       = (const float*)d_in[12];
    float* out = (float*)d_out;

    int n = in_sizes[0] / FIN;     // 50000
    int e = in_sizes[1];           // 1600000

    cudaFuncSetAttribute(spmmW_kernel<true>,  cudaFuncAttributeMaxDynamicSharedMemorySize, SPMM_SMEM);
    cudaFuncSetAttribute(spmmW_kernel<false>, cudaFuncAttributeMaxDynamicSharedMemorySize, SPMM_SMEM);

    int edgeBlocks = (e + 255) / 256;
    dim3 gemmGrid(NP / GBM, HH / GBN);   // 391 x 2

    hist_kernel<<<edgeBlocks, 256>>>(dst, e);                                  // 1
    scan_kernel<<<1, 1024>>>(n);                                               // 2
    scatter_kernel<<<edgeBlocks, 256>>>(src, dst, ew, e);                      // 3
    gemmT_kernel<true,  false><<<gemmGrid, 256>>>(features, W1, g_xT, n, FIN); // 4  <-- profiled
    spmmW_kernel<true><<<HH, 1024, SPMM_SMEM>>>(g_xT, g_hT, b1, n);            // 5
    gemmT_kernel<false, true ><<<gemmGrid, 256>>>(g_hT, W2, g_xT, n, HH);      // 6
    spmmW_kernel<false><<<HH, 1024, SPMM_SMEM>>>(g_xT, g_hT, b2, n);           // 7
    wcomb_kernel<<<7, 256>>>(We, be, Wf, bf);                                  // 8
    head_kernel<<<(n + 31) / 32, 128>>>(g_hT, y, Wf, out, n);                  // 9
}

// round 11
// speedup vs baseline: 3.8696x; 2.8168x over previous
#include <cuda_runtime.h>
#include <cuda_bf16.h>
#include <math.h>

// Problem constants (match reference)
#define NN 50000
#define EE 1600000
#define EEP 2100000         // padded edge capacity (EE + 8*NN slack)
#define FIN 256
#define HH 128
#define CC 40
#define NP 50048            // NN padded to multiple of 128 (pad rows stay 0)

// ---------------- device scratch (no allocs allowed) ----------------
__device__ __align__(16) float g_xT[(size_t)HH * NP];  // feature-major buffer A
__device__ __align__(16) float g_hT[(size_t)HH * NP];  // feature-major buffer B
__device__ int   g_deg[NN];            // zero at load; scan re-zeroes after use
__device__ int   g_rowptrP[NN + 1];    // 8-padded CSR offsets
__device__ int   g_cursor[NN];
__device__ __align__(16) unsigned short g_esrc16[EEP]; // src per edge (u16); pads untouched (0)
__device__ __align__(16) float          g_ew[EEP];     // weight per edge; pads stay 0.0f
__device__ float g_Wc[CC * CC];
__device__ float g_cbias[CC];

// ---------------- CSR build ----------------
__global__ void hist_kernel(const int* __restrict__ dst, int e) {
    int i = blockIdx.x * blockDim.x + threadIdx.x;
    if (i < e) atomicAdd(&g_deg[dst[i]], 1);
}
// prefix-sum over per-row padded degree ceil(deg/8)*8; also re-zeroes g_deg
__global__ void scan_kernel(int n) {
    __shared__ int wsum[32];
    __shared__ int s_run;
    int tid = threadIdx.x, lane = tid & 31, wid = tid >> 5;
    if (tid == 0) s_run = 0;
    __syncthreads();
    for (int base = 0; base < n; base += 1024) {
        int idx = base + tid;
        int dp = 0;
        if (idx < n) { int v = g_deg[idx]; g_deg[idx] = 0; dp = (v + 7) & ~7; }
        int inc = dp;
        #pragma unroll
        for (int off = 1; off < 32; off <<= 1) {
            int t = __shfl_up_sync(0xffffffffu, inc, off);
            if (lane >= off) inc += t;
        }
        if (lane == 31) wsum[wid] = inc;
        __syncthreads();
        if (wid == 0) {
            int x = wsum[lane];
            #pragma unroll
            for (int off = 1; off < 32; off <<= 1) {
                int t = __shfl_up_sync(0xffffffffu, x, off);
                if (lane >= off) x += t;
            }
            wsum[lane] = x;
        }
        __syncthreads();
        int woff = (wid > 0) ? wsum[wid - 1] : 0;
        int run = s_run;
        int excl = run + woff + inc - dp;
        if (idx < n) { g_rowptrP[idx] = excl; g_cursor[idx] = excl; }
        __syncthreads();
        if (tid == 0) s_run = run + wsum[31];
        __syncthreads();
    }
    if (threadIdx.x == 0) g_rowptrP[n] = s_run;
}
__global__ void scatter_kernel(const int* __restrict__ src, const int* __restrict__ dst,
                               const float* __restrict__ w, int e) {
    int i = blockIdx.x * blockDim.x + threadIdx.x;
    if (i < e) {
        int d = dst[i];
        int pos = atomicAdd(&g_cursor[d], 1);
        g_esrc16[pos] = (unsigned short)src[i];
        g_ew[pos]     = w[i];
    }
}

// ---------------- GEMM with transposed (feature-major) output ----------------
#define GBM 128
#define GBN 64
#define GBK 8
template<bool NORM, bool AFM>
__global__ __launch_bounds__(256, 3) void gemmT_kernel(
    const float* __restrict__ A, const float* __restrict__ B,
    float* __restrict__ CT, int M, int K)
{
    __shared__ float As[2][GBK][GBM + 4];
    __shared__ float Bs[2][GBK][GBN];
    __shared__ float sT[GBN][GBM + 1];
    __shared__ float s_invs[GBM];
    int tid = threadIdx.x;
    int m0 = blockIdx.x * GBM;
    int n0 = blockIdx.y * GBN;
    int tx = tid & 15, ty = tid >> 4;

    int arow = tid >> 1;
    int ahalf = (tid & 1) * 4;
    bool aok = (m0 + arow) < M;
    const float* Aptr = A + (size_t)(m0 + arow) * K + ahalf;
    int akk = tid >> 5;
    int ac4 = (tid & 31) * 4;
    const float* AptrF = A + (size_t)akk * NP + m0 + ac4;
    int brow = tid >> 5;
    int bcol = (tid & 31) * 2;
    const float* Bptr = B + (size_t)brow * HH + n0 + bcol;

    float acc[8][4];
    #pragma unroll
    for (int i = 0; i < 8; i++)
        #pragma unroll
        for (int j = 0; j < 4; j++) acc[i][j] = 0.0f;
    float ssq = 0.0f;

    float4 areg;
    if (AFM) {
        areg = *(const float4*)AptrF;
    } else {
        areg = make_float4(0.f, 0.f, 0.f, 0.f);
        if (aok) areg = *(const float4*)Aptr;
        if (NORM) ssq += areg.x*areg.x + areg.y*areg.y + areg.z*areg.z + areg.w*areg.w;
    }
    float2 breg = *(const float2*)Bptr;

    if (AFM) {
        *(float4*)&As[0][akk][ac4] = areg;
    } else {
        As[0][ahalf + 0][arow] = areg.x;
        As[0][ahalf + 1][arow] = areg.y;
        As[0][ahalf + 2][arow] = areg.z;
        As[0][ahalf + 3][arow] = areg.w;
    }
    Bs[0][brow][bcol] = breg.x;
    Bs[0][brow][bcol + 1] = breg.y;
    __syncthreads();

    int buf = 0;
    for (int k0 = GBK; k0 < K; k0 += GBK) {
        if (AFM) {
            areg = *(const float4*)(AptrF + (size_t)k0 * NP);
        } else {
            areg = make_float4(0.f, 0.f, 0.f, 0.f);
            if (aok) areg = *(const float4*)(Aptr + k0);
            if (NORM) ssq += areg.x*areg.x + areg.y*areg.y + areg.z*areg.z + areg.w*areg.w;
        }
        breg = *(const float2*)(Bptr + (size_t)k0 * HH);

        #pragma unroll
        for (int kk = 0; kk < GBK; kk++) {
            float ra[8], rb[4];
            *(float4*)(ra)     = *(const float4*)&As[buf][kk][ty * 8];
            *(float4*)(ra + 4) = *(const float4*)&As[buf][kk][ty * 8 + 4];
            *(float4*)(rb)     = *(const float4*)&Bs[buf][kk][tx * 4];
            #pragma unroll
            for (int i = 0; i < 8; i++)
                #pragma unroll
                for (int j = 0; j < 4; j++) acc[i][j] += ra[i] * rb[j];
        }
        int nb = buf ^ 1;
        if (AFM) {
            *(float4*)&As[nb][akk][ac4] = areg;
        } else {
            As[nb][ahalf + 0][arow] = areg.x;
            As[nb][ahalf + 1][arow] = areg.y;
            As[nb][ahalf + 2][arow] = areg.z;
            As[nb][ahalf + 3][arow] = areg.w;
        }
        Bs[nb][brow][bcol] = breg.x;
        Bs[nb][brow][bcol + 1] = breg.y;
        __syncthreads();
        buf = nb;
    }
    #pragma unroll
    for (int kk = 0; kk < GBK; kk++) {
        float ra[8], rb[4];
        *(float4*)(ra)     = *(const float4*)&As[buf][kk][ty * 8];
        *(float4*)(ra + 4) = *(const float4*)&As[buf][kk][ty * 8 + 4];
        *(float4*)(rb)     = *(const float4*)&Bs[buf][kk][tx * 4];
        #pragma unroll
        for (int i = 0; i < 8; i++)
            #pragma unroll
            for (int j = 0; j < 4; j++) acc[i][j] += ra[i] * rb[j];
    }

    if (NORM) {
        float tot = ssq + __shfl_xor_sync(0xffffffffu, ssq, 1);
        s_invs[arow] = 1.0f / fmaxf(sqrtf(tot), 1e-12f);
    }
    __syncthreads();

    #pragma unroll
    for (int i = 0; i < 8; i++) {
        float s = NORM ? s_invs[ty * 8 + i] : 1.0f;
        #pragma unroll
        for (int j = 0; j < 4; j++) sT[tx * 4 + j][ty * 8 + i] = acc[i][j] * s;
    }
    __syncthreads();
    #pragma unroll
    for (int t = 0; t < 32; t++) {
        int lin = tid + t * 256;
        int c = lin >> 7;
        int r = lin & 127;
        int gr = m0 + r;
        if (gr < M) CT[(size_t)(n0 + c) * NP + gr] = sT[c][r];
    }
}

// ---------------- feature-major SPMM, thread-per-row, 8-edge vector loads ----------------
// One CTA per feature f; sx = xT[f][:] in smem. Each thread handles rows
// tid, tid+1024, ... Its row's edge segment is 8-padded and 16B-aligned:
// 8 edges = one int4 (8 u16 srcs) + two int4 (8 f32 weights) = 3 wavefront-
// heavy loads instead of 8. Pads have w=0 and contribute nothing.
template<bool RELU>
__global__ __launch_bounds__(1024) void spmmT_kernel(
    const float* __restrict__ xT, float* __restrict__ outT,
    const float* __restrict__ bias, int n)
{
    extern __shared__ float sx[];
    int f = blockIdx.x;
    const float* xrow = xT + (size_t)f * NP;
    for (int i = threadIdx.x; i < n; i += 1024) sx[i] = xrow[i];
    __syncthreads();
    float b = bias[f];
    float* orow = outT + (size_t)f * NP;

    for (int row = threadIdx.x; row < n; row += 1024) {
        int e0 = g_rowptrP[row], e1 = g_rowptrP[row + 1];
        float acc = b;
        for (int e = e0; e < e1; e += 8) {
            int4 s  = *(const int4*)(g_esrc16 + e);   // 8 x u16 src
            int4 wa = *(const int4*)(g_ew + e);       // 4 x f32 w
            int4 wb = *(const int4*)(g_ew + e + 4);   // 4 x f32 w
            acc += __int_as_float(wa.x) * sx[(unsigned)s.x & 0xFFFFu];
            acc += __int_as_float(wa.y) * sx[(unsigned)s.x >> 16];
            acc += __int_as_float(wa.z) * sx[(unsigned)s.y & 0xFFFFu];
            acc += __int_as_float(wa.w) * sx[(unsigned)s.y >> 16];
            acc += __int_as_float(wb.x) * sx[(unsigned)s.z & 0xFFFFu];
            acc += __int_as_float(wb.y) * sx[(unsigned)s.z >> 16];
            acc += __int_as_float(wb.z) * sx[(unsigned)s.w & 0xFFFFu];
            acc += __int_as_float(wb.w) * sx[(unsigned)s.w >> 16];
        }
        if (RELU) acc = fmaxf(acc, 0.f);
        orow[row] = acc;
    }
}

// ---------------- head weight pre-combine ----------------
__global__ void wcomb_kernel(const float* __restrict__ We, const float* __restrict__ be,
                             const float* __restrict__ Wf, const float* __restrict__ bf)
{
    int t = blockIdx.x * blockDim.x + threadIdx.x;
    if (t < CC * CC) {
        int i = t / CC, c = t % CC;
        float s = 0.f;
        for (int k = 0; k < HH; k++) s += We[i * HH + k] * Wf[k * CC + c];
        g_Wc[t] = s;
    }
    if (t < CC) {
        float s = bf[t];
        for (int k = 0; k < HH; k++) s += be[k] * Wf[k * CC + t];
        g_cbias[t] = s;
    }
}

// ---------------- fused head: logits = y@Wc + h@Wf_bot + cbias ; softmax ----------------
__global__ __launch_bounds__(128) void head_kernel(
    const float* __restrict__ hT, const float* __restrict__ yin,
    const float* __restrict__ Wf, float* __restrict__ out, int n)
{
    __shared__ float sWfb[HH * CC];
    __shared__ float sWc[CC * CC];
    __shared__ float sh[32 * 129];
    __shared__ float sl[32 * CC];
    __shared__ float smax[32], sinv[32];
    int tid = threadIdx.x;
    int r0 = blockIdx.x * 32;
    int rows = min(32, n - r0);

    for (int i = tid; i < HH * CC; i += 128) sWfb[i] = Wf[HH * CC + i];
    for (int i = tid; i < CC * CC; i += 128) sWc[i] = g_Wc[i];
    for (int i = tid; i < 32 * HH; i += 128) {
        int k = i >> 5, r = i & 31;
        if (r < rows) sh[r * 129 + k] = hT[(size_t)k * NP + r0 + r];
    }
    __syncthreads();

    int r = tid >> 2, q = tid & 3, c0 = q * 10;
    if (r < rows) {
        float acc[10];
        #pragma unroll
        for (int j = 0; j < 10; j++) acc[j] = g_cbias[c0 + j];
        for (int k = 0; k < HH; k++) {
            float hv = sh[r * 129 + k];
            #pragma unroll
            for (int j = 0; j < 10; j++) acc[j] += hv * sWfb[k * CC + c0 + j];
        }
        const float* yr = yin + (size_t)(r0 + r) * CC;
        for (int k = 0; k < CC; k++) {
            float yv = yr[k];
            #pragma unroll
            for (int j = 0; j < 10; j++) acc[j] += yv * sWc[k * CC + c0 + j];
        }
        #pragma unroll
        for (int j = 0; j < 10; j++) sl[r * CC + c0 + j] = acc[j];
    }
    __syncthreads();
    if (tid < 32 && tid < rows) {
        float m = -1e30f;
        for (int c = 0; c < CC; c++) m = fmaxf(m, sl[tid * CC + c]);
        float s = 0.f;
        for (int c = 0; c < CC; c++) s += __expf(sl[tid * CC + c] - m);
        smax[tid] = m;
        sinv[tid] = 1.0f / s;
    }
    __syncthreads();
    int tot = rows * CC;
    for (int i = tid; i < tot; i += 128) {
        int rr = i / CC;
        out[(size_t)r0 * CC + i] = __expf(sl[i] - smax[rr]) * sinv[rr];
    }
}

// ---------------- launch ----------------
#define SPMM_SMEM (NN * 4)   // 200000 B < 227KB cap

extern "C" void kernel_launch(void* const* d_in, const int* in_sizes, int n_in,
                              void* d_out, int out_size)
{
    const float* features = (const float*)d_in[0];
    const int*   src      = (const int*)  d_in[1];
    const int*   dst      = (const int*)  d_in[2];
    const float* ew       = (const float*)d_in[3];
    const float* y        = (const float*)d_in[4];
    const float* W1       = (const float*)d_in[5];
    const float* b1       = (const float*)d_in[6];
    const float* W2       = (const float*)d_in[7];
    const float* b2       = (const float*)d_in[8];
    const float* We       = (const float*)d_in[9];
    const float* be       = (const float*)d_in[10];
    const float* Wf       = (const float*)d_in[11];
    const float* bf       = (const float*)d_in[12];
    float* out = (float*)d_out;

    int n = in_sizes[0] / FIN;     // 50000
    int e = in_sizes[1];           // 1600000

    cudaFuncSetAttribute(spmmT_kernel<true>,  cudaFuncAttributeMaxDynamicSharedMemorySize, SPMM_SMEM);
    cudaFuncSetAttribute(spmmT_kernel<false>, cudaFuncAttributeMaxDynamicSharedMemorySize, SPMM_SMEM);

    int edgeBlocks = (e + 255) / 256;
    dim3 gemmGrid(NP / GBM, HH / GBN);   // 391 x 2

    hist_kernel<<<edgeBlocks, 256>>>(dst, e);                                  // 1
    scan_kernel<<<1, 1024>>>(n);                                               // 2
    scatter_kernel<<<edgeBlocks, 256>>>(src, dst, ew, e);                      // 3
    gemmT_kernel<true,  false><<<gemmGrid, 256>>>(features, W1, g_xT, n, FIN); // 4  <-- profiled
    spmmT_kernel<true><<<HH, 1024, SPMM_SMEM>>>(g_xT, g_hT, b1, n);            // 5
    gemmT_kernel<false, true ><<<gemmGrid, 256>>>(g_hT, W2, g_xT, n, HH);      // 6
    spmmT_kernel<false><<<HH, 1024, SPMM_SMEM>>>(g_xT, g_hT, b2, n);           // 7
    wcomb_kernel<<<7, 256>>>(We, be, Wf, bf);                                  // 8
    head_kernel<<<(n + 31) / 32, 128>>>(g_hT, y, Wf, out, n);                  // 9
}

// round 13
// speedup vs baseline: 4.5901x; 1.1862x over previous
#include <cuda_runtime.h>
#include <cuda_bf16.h>
#include <math.h>

// Problem constants (match reference)
#define NN 50000
#define EEP 3200000         // lane-interleaved padded edge capacity (~1.5x E)
#define FIN 256
#define HH 128
#define CC 40
#define NP 50048            // NN padded to multiple of 128 (pad rows stay 0)
#define NGMAX 1564          // (NN+31)/32 = 1563 groups (+1 for base array)

// ---------------- device scratch (no allocs allowed) ----------------
__device__ __align__(16) float g_xT[(size_t)HH * NP];  // feature-major buffer A
__device__ __align__(16) float g_hT[(size_t)HH * NP];  // feature-major buffer B
__device__ int   g_deg[NN];            // zero at load; scan re-zeroes after use
__device__ int   g_gbase[NGMAX + 1];   // per-32-row-group padded base offsets
__device__ int   g_cursor[NN];         // per-row edge cursor (scan zeroes it)
__device__ __align__(16) unsigned short g_esrc16[EEP]; // lane-interleaved src; pads 0
__device__ __align__(16) float          g_ew[EEP];     // lane-interleaved w;  pads 0.0f
__device__ float g_Wc[CC * CC];
__device__ float g_cbias[CC];

// ---------------- CSR/ELL build ----------------
__global__ void hist_kernel(const int* __restrict__ dst, int e) {
    int i = blockIdx.x * blockDim.x + threadIdx.x;
    if (i < e) atomicAdd(&g_deg[dst[i]], 1);
}
// per-group max degree (rounded up to 8) -> prefix sum of 32*max; zeroes deg+cursor
__global__ void scan_kernel(int n) {
    __shared__ int wsum[32];
    __shared__ int s_run;
    int tid = threadIdx.x, lane = tid & 31, wid = tid >> 5;
    int ngroups = (n + 31) >> 5;
    if (tid == 0) s_run = 0;
    __syncthreads();
    for (int base = 0; base < ngroups; base += 1024) {
        int g = base + tid;
        int dp = 0;
        if (g < ngroups) {
            int m = 0;
            #pragma unroll 4
            for (int r = 0; r < 32; r++) {
                int row = g * 32 + r;
                if (row < n) {
                    int v = g_deg[row];
                    g_deg[row] = 0;
                    g_cursor[row] = 0;
                    m = max(m, v);
                }
            }
            m = (m + 7) & ~7;          // uniform, unroll-8-friendly
            dp = m * 32;
        }
        int inc = dp;
        #pragma unroll
        for (int off = 1; off < 32; off <<= 1) {
            int t = __shfl_up_sync(0xffffffffu, inc, off);
            if (lane >= off) inc += t;
        }
        if (lane == 31) wsum[wid] = inc;
        __syncthreads();
        if (wid == 0) {
            int x = wsum[lane];
            #pragma unroll
            for (int off = 1; off < 32; off <<= 1) {
                int t = __shfl_up_sync(0xffffffffu, x, off);
                if (lane >= off) x += t;
            }
            wsum[lane] = x;
        }
        __syncthreads();
        int woff = (wid > 0) ? wsum[wid - 1] : 0;
        int run = s_run;
        if (g < ngroups) g_gbase[g] = run + woff + inc - dp;
        __syncthreads();
        if (tid == 0) s_run = run + wsum[31];
        __syncthreads();
    }
    if (threadIdx.x == 0) g_gbase[ngroups] = s_run;
}
// edge j of row d lands at gbase[d>>5] + j*32 + (d&31)
__global__ void scatter_kernel(const int* __restrict__ src, const int* __restrict__ dst,
                               const float* __restrict__ w, int e) {
    int i = blockIdx.x * blockDim.x + threadIdx.x;
    if (i < e) {
        int d = dst[i];
        int j = atomicAdd(&g_cursor[d], 1);
        int pos = g_gbase[d >> 5] + j * 32 + (d & 31);
        g_esrc16[pos] = (unsigned short)src[i];
        g_ew[pos]     = w[i];
    }
}

// ---------------- GEMM with transposed (feature-major) output ----------------
#define GBM 128
#define GBN 64
#define GBK 8
template<bool NORM, bool AFM>
__global__ __launch_bounds__(256, 3) void gemmT_kernel(
    const float* __restrict__ A, const float* __restrict__ B,
    float* __restrict__ CT, int M, int K)
{
    __shared__ float As[2][GBK][GBM + 4];
    __shared__ float Bs[2][GBK][GBN];
    __shared__ float sT[GBN][GBM + 1];
    __shared__ float s_invs[GBM];
    int tid = threadIdx.x;
    int m0 = blockIdx.x * GBM;
    int n0 = blockIdx.y * GBN;
    int tx = tid & 15, ty = tid >> 4;

    int arow = tid >> 1;
    int ahalf = (tid & 1) * 4;
    bool aok = (m0 + arow) < M;
    const float* Aptr = A + (size_t)(m0 + arow) * K + ahalf;
    int akk = tid >> 5;
    int ac4 = (tid & 31) * 4;
    const float* AptrF = A + (size_t)akk * NP + m0 + ac4;
    int brow = tid >> 5;
    int bcol = (tid & 31) * 2;
    const float* Bptr = B + (size_t)brow * HH + n0 + bcol;

    float acc[8][4];
    #pragma unroll
    for (int i = 0; i < 8; i++)
        #pragma unroll
        for (int j = 0; j < 4; j++) acc[i][j] = 0.0f;
    float ssq = 0.0f;

    float4 areg;
    if (AFM) {
        areg = *(const float4*)AptrF;
    } else {
        areg = make_float4(0.f, 0.f, 0.f, 0.f);
        if (aok) areg = *(const float4*)Aptr;
        if (NORM) ssq += areg.x*areg.x + areg.y*areg.y + areg.z*areg.z + areg.w*areg.w;
    }
    float2 breg = *(const float2*)Bptr;

    if (AFM) {
        *(float4*)&As[0][akk][ac4] = areg;
    } else {
        As[0][ahalf + 0][arow] = areg.x;
        As[0][ahalf + 1][arow] = areg.y;
        As[0][ahalf + 2][arow] = areg.z;
        As[0][ahalf + 3][arow] = areg.w;
    }
    Bs[0][brow][bcol] = breg.x;
    Bs[0][brow][bcol + 1] = breg.y;
    __syncthreads();

    int buf = 0;
    for (int k0 = GBK; k0 < K; k0 += GBK) {
        if (AFM) {
            areg = *(const float4*)(AptrF + (size_t)k0 * NP);
        } else {
            areg = make_float4(0.f, 0.f, 0.f, 0.f);
            if (aok) areg = *(const float4*)(Aptr + k0);
            if (NORM) ssq += areg.x*areg.x + areg.y*areg.y + areg.z*areg.z + areg.w*areg.w;
        }
        breg = *(const float2*)(Bptr + (size_t)k0 * HH);

        #pragma unroll
        for (int kk = 0; kk < GBK; kk++) {
            float ra[8], rb[4];
            *(float4*)(ra)     = *(const float4*)&As[buf][kk][ty * 8];
            *(float4*)(ra + 4) = *(const float4*)&As[buf][kk][ty * 8 + 4];
            *(float4*)(rb)     = *(const float4*)&Bs[buf][kk][tx * 4];
            #pragma unroll
            for (int i = 0; i < 8; i++)
                #pragma unroll
                for (int j = 0; j < 4; j++) acc[i][j] += ra[i] * rb[j];
        }
        int nb = buf ^ 1;
        if (AFM) {
            *(float4*)&As[nb][akk][ac4] = areg;
        } else {
            As[nb][ahalf + 0][arow] = areg.x;
            As[nb][ahalf + 1][arow] = areg.y;
            As[nb][ahalf + 2][arow] = areg.z;
            As[nb][ahalf + 3][arow] = areg.w;
        }
        Bs[nb][brow][bcol] = breg.x;
        Bs[nb][brow][bcol + 1] = breg.y;
        __syncthreads();
        buf = nb;
    }
    #pragma unroll
    for (int kk = 0; kk < GBK; kk++) {
        float ra[8], rb[4];
        *(float4*)(ra)     = *(const float4*)&As[buf][kk][ty * 8];
        *(float4*)(ra + 4) = *(const float4*)&As[buf][kk][ty * 8 + 4];
        *(float4*)(rb)     = *(const float4*)&Bs[buf][kk][tx * 4];
        #pragma unroll
        for (int i = 0; i < 8; i++)
            #pragma unroll
            for (int j = 0; j < 4; j++) acc[i][j] += ra[i] * rb[j];
    }

    if (NORM) {
        float tot = ssq + __shfl_xor_sync(0xffffffffu, ssq, 1);
        s_invs[arow] = 1.0f / fmaxf(sqrtf(tot), 1e-12f);
    }
    __syncthreads();

    #pragma unroll
    for (int i = 0; i < 8; i++) {
        float s = NORM ? s_invs[ty * 8 + i] : 1.0f;
        #pragma unroll
        for (int j = 0; j < 4; j++) sT[tx * 4 + j][ty * 8 + i] = acc[i][j] * s;
    }
    __syncthreads();
    #pragma unroll
    for (int t = 0; t < 32; t++) {
        int lin = tid + t * 256;
        int c = lin >> 7;
        int r = lin & 127;
        int gr = m0 + r;
        if (gr < M) CT[(size_t)(n0 + c) * NP + gr] = sT[c][r];
    }
}

// ---------------- feature-major SPMM, lane-interleaved edges ----------------
// One CTA per feature f; sx = xT[f][:] in smem. Warp w handles row-groups
// w, w+32, ... (group = 32 consecutive rows; lane = row within group).
// At step j the warp reads 32 contiguous u16 srcs (1 line) + 32 contiguous
// f32 ws (1 line) — fully coalesced. Group loop count is uniform across the
// warp (padded to max degree, mult of 8); pads have w=0.
template<bool RELU>
__global__ __launch_bounds__(1024) void spmmG_kernel(
    const float* __restrict__ xT, float* __restrict__ outT,
    const float* __restrict__ bias, int n)
{
    extern __shared__ float sx[];
    int f = blockIdx.x;
    const float* xrow = xT + (size_t)f * NP;
    for (int i = threadIdx.x; i < n; i += 1024) sx[i] = xrow[i];
    __syncthreads();
    float b = bias[f];
    float* orow = outT + (size_t)f * NP;
    int warp = threadIdx.x >> 5, lane = threadIdx.x & 31;
    int ngroups = (n + 31) >> 5;

    for (int g = warp; g < ngroups; g += 32) {
        int base = g_gbase[g];
        int iters = (g_gbase[g + 1] - base) >> 5;   // multiple of 8
        const unsigned short* sp = g_esrc16 + base + lane;
        const float*          wp = g_ew     + base + lane;
        float acc = b;
        for (int j = 0; j < iters; j += 8) {
            unsigned short s0 = sp[0],   s1 = sp[32],  s2 = sp[64],  s3 = sp[96];
            unsigned short s4 = sp[128], s5 = sp[160], s6 = sp[192], s7 = sp[224];
            float w0 = wp[0],   w1 = wp[32],  w2 = wp[64],  w3 = wp[96];
            float w4 = wp[128], w5 = wp[160], w6 = wp[192], w7 = wp[224];
            acc += w0 * sx[s0];
            acc += w1 * sx[s1];
            acc += w2 * sx[s2];
            acc += w3 * sx[s3];
            acc += w4 * sx[s4];
            acc += w5 * sx[s5];
            acc += w6 * sx[s6];
            acc += w7 * sx[s7];
            sp += 256; wp += 256;
        }
        int row = g * 32 + lane;
        if (row < n) {
            if (RELU) acc = fmaxf(acc, 0.f);
            orow[row] = acc;
        }
    }
}

// ---------------- head weight pre-combine ----------------
__global__ void wcomb_kernel(const float* __restrict__ We, const float* __restrict__ be,
                             const float* __restrict__ Wf, const float* __restrict__ bf)
{
    int t = blockIdx.x * blockDim.x + threadIdx.x;
    if (t < CC * CC) {
        int i = t / CC, c = t % CC;
        float s = 0.f;
        for (int k = 0; k < HH; k++) s += We[i * HH + k] * Wf[k * CC + c];
        g_Wc[t] = s;
    }
    if (t < CC) {
        float s = bf[t];
        for (int k = 0; k < HH; k++) s += be[k] * Wf[k * CC + t];
        g_cbias[t] = s;
    }
}

// ---------------- fused head: logits = y@Wc + h@Wf_bot + cbias ; softmax ----------------
__global__ __launch_bounds__(128) void head_kernel(
    const float* __restrict__ hT, const float* __restrict__ yin,
    const float* __restrict__ Wf, float* __restrict__ out, int n)
{
    __shared__ float sWfb[HH * CC];
    __shared__ float sWc[CC * CC];
    __shared__ float sh[32 * 129];
    __shared__ float sl[32 * CC];
    __shared__ float smax[32], sinv[32];
    int tid = threadIdx.x;
    int r0 = blockIdx.x * 32;
    int rows = min(32, n - r0);

    for (int i = tid; i < HH * CC; i += 128) sWfb[i] = Wf[HH * CC + i];
    for (int i = tid; i < CC * CC; i += 128) sWc[i] = g_Wc[i];
    for (int i = tid; i < 32 * HH; i += 128) {
        int k = i >> 5, r = i & 31;
        if (r < rows) sh[r * 129 + k] = hT[(size_t)k * NP + r0 + r];
    }
    __syncthreads();

    int r = tid >> 2, q = tid & 3, c0 = q * 10;
    if (r < rows) {
        float acc[10];
        #pragma unroll
        for (int j = 0; j < 10; j++) acc[j] = g_cbias[c0 + j];
        for (int k = 0; k < HH; k++) {
            float hv = sh[r * 129 + k];
            #pragma unroll
            for (int j = 0; j < 10; j++) acc[j] += hv * sWfb[k * CC + c0 + j];
        }
        const float* yr = yin + (size_t)(r0 + r) * CC;
        for (int k = 0; k < CC; k++) {
            float yv = yr[k];
            #pragma unroll
            for (int j = 0; j < 10; j++) acc[j] += yv * sWc[k * CC + c0 + j];
        }
        #pragma unroll
        for (int j = 0; j < 10; j++) sl[r * CC + c0 + j] = acc[j];
    }
    __syncthreads();
    if (tid < 32 && tid < rows) {
        float m = -1e30f;
        for (int c = 0; c < CC; c++) m = fmaxf(m, sl[tid * CC + c]);
        float s = 0.f;
        for (int c = 0; c < CC; c++) s += __expf(sl[tid * CC + c] - m);
        smax[tid] = m;
        sinv[tid] = 1.0f / s;
    }
    __syncthreads();
    int tot = rows * CC;
    for (int i = tid; i < tot; i += 128) {
        int rr = i / CC;
        out[(size_t)r0 * CC + i] = __expf(sl[i] - smax[rr]) * sinv[rr];
    }
}

// ---------------- launch ----------------
#define SPMM_SMEM (NN * 4)   // 200000 B < 227KB cap

extern "C" void kernel_launch(void* const* d_in, const int* in_sizes, int n_in,
                              void* d_out, int out_size)
{
    const float* features = (const float*)d_in[0];
    const int*   src      = (const int*)  d_in[1];
    const int*   dst      = (const int*)  d_in[2];
    const float* ew       = (const float*)d_in[3];
    const float* y        = (const float*)d_in[4];
    const float* W1       = (const float*)d_in[5];
    const float* b1       = (const float*)d_in[6];
    const float* W2       = (const float*)d_in[7];
    const float* b2       = (const float*)d_in[8];
    const float* We       = (const float*)d_in[9];
    const float* be       = (const float*)d_in[10];
    const float* Wf       = (const float*)d_in[11];
    const float* bf       = (const float*)d_in[12];
    float* out = (float*)d_out;

    int n = in_sizes[0] / FIN;     // 50000
    int e = in_sizes[1];           // 1600000

    cudaFuncSetAttribute(spmmG_kernel<true>,  cudaFuncAttributeMaxDynamicSharedMemorySize, SPMM_SMEM);
    cudaFuncSetAttribute(spmmG_kernel<false>, cudaFuncAttributeMaxDynamicSharedMemorySize, SPMM_SMEM);

    int edgeBlocks = (e + 255) / 256;
    dim3 gemmGrid(NP / GBM, HH / GBN);   // 391 x 2

    hist_kernel<<<edgeBlocks, 256>>>(dst, e);                                  // 1
    scan_kernel<<<1, 1024>>>(n);                                               // 2
    scatter_kernel<<<edgeBlocks, 256>>>(src, dst, ew, e);                      // 3
    gemmT_kernel<true,  false><<<gemmGrid, 256>>>(features, W1, g_xT, n, FIN); // 4  <-- profiled
    spmmG_kernel<true><<<HH, 1024, SPMM_SMEM>>>(g_xT, g_hT, b1, n);            // 5
    gemmT_kernel<false, true ><<<gemmGrid, 256>>>(g_hT, W2, g_xT, n, HH);      // 6
    spmmG_kernel<false><<<HH, 1024, SPMM_SMEM>>>(g_xT, g_hT, b2, n);           // 7
    wcomb_kernel<<<7, 256>>>(We, be, Wf, bf);                                  // 8
    head_kernel<<<(n + 31) / 32, 128>>>(g_hT, y, Wf, out, n);                  // 9
}